// round 14
// baseline (speedup 1.0000x reference)
#include <cuda_runtime.h>
#include <cstdint>
#include <cmath>

#define HIDDEN 768
#define NHEADS 12
#define HDIM 64
#define BB 8
#define SS 512
#define ROWS (BB*SS)              // 4096
#define HEADROWS (BB*NHEADS*SS)   // 49152

// ---------------- scratch (static device allocations; no cudaMalloc) ----------------
__device__ float g_XdT[(size_t)HIDDEN*ROWS];       // dequant hidden_states, TRANSPOSED [k][m]
__device__ float g_WdT[(size_t)3*HIDDEN*HIDDEN];   // dequant Wq|Wk|Wv, each TRANSPOSED [k][n]
__device__ float g_Wod[(size_t)HIDDEN*HIDDEN];     // dequant Wo (row-major)
__device__ float g_Qd[(size_t)HEADROWS*HDIM];      // dequant per-head q
__device__ float g_Kd[(size_t)HEADROWS*HDIM];
__device__ float g_Vd[(size_t)HEADROWS*HDIM];
__device__ float g_P [(size_t)HEADROWS*SS];        // scores, then (in-place) dequant probs
__device__ float g_CTX[(size_t)ROWS*HIDDEN];
__device__ float g_Cd[(size_t)ROWS*HIDDEN];        // dequant quantized ctx (row-major)

struct PLA { float m[12]; float c[12]; float iv[13]; };

typedef unsigned long long ull;

// packed f32x2 ops: two independent IEEE RN ops in one instruction
__device__ __forceinline__ ull ffma2(ull a, ull b, ull c) {
    ull d;
    asm("fma.rn.f32x2 %0, %1, %2, %3;" : "=l"(d) : "l"(a), "l"(b), "l"(c));
    return d;
}
__device__ __forceinline__ ull fmul2(ull a, ull b) {
    ull d;
    asm("mul.rn.f32x2 %0, %1, %2;" : "=l"(d) : "l"(a), "l"(b));
    return d;
}
__device__ __forceinline__ float2 up2(ull v) {
    float2 r;
    asm("mov.b64 {%0, %1}, %2;" : "=f"(r.x), "=f"(r.y) : "l"(v));
    return r;
}
__device__ __forceinline__ ull dup2(float x) {
    ull d;
    asm("mov.b64 %0, {%1, %1};" : "=l"(d) : "f"(x));
    return d;
}
__device__ __forceinline__ ull pk2(float a, float b) {
    ull d;
    asm("mov.b64 %0, {%1, %2};" : "=l"(d) : "f"(a), "f"(b));
    return d;
}
// Markstein correctly-rounded division given y = __frcp_rn(d). Bit-identical to __fdiv_rn(v,d).
__device__ __forceinline__ float divm(float v, float d, float y) {
    float q0 = __fmul_rn(v, y);
    float r  = __fmaf_rn(-q0, d, v);
    return __fmaf_rn(r, y, q0);
}
// packed Markstein: dn = dup2(-d), yp = dup2(y). Per-lane bit-identical to divm.
__device__ __forceinline__ ull divm2(ull vp, ull dn, ull yp) {
    ull q0 = fmul2(vp, yp);
    ull r  = ffma2(q0, dn, vp);
    return ffma2(r, yp, q0);
}
// cp.async 16B gmem -> smem
__device__ __forceinline__ void cpa16(void* smp, const void* gmp) {
    unsigned s = (unsigned)__cvta_generic_to_shared(smp);
    asm volatile("cp.async.cg.shared.global [%0], [%1], 16;" :: "r"(s), "l"(gmp));
}

// ---------------- warp-per-row (768) quantize: compute v[24] in regs ----------------
__device__ __forceinline__ void wrow_calc(const float* __restrict__ x, float* v, int lane) {
    #pragma unroll
    for (int j=0;j<6;j++) *(float4*)&v[j*4] = *(const float4*)&x[j*128 + lane*4];
    float mx = fabsf(v[0]);
    #pragma unroll
    for (int j=1;j<24;j++) mx = fmaxf(mx, fabsf(v[j]));
    #pragma unroll
    for (int o=16;o>0;o>>=1) mx = fmaxf(mx, __shfl_xor_sync(0xffffffffu, mx, o));
    float sc = __fdiv_rn(mx, 127.0f);
    if (sc == 0.0f) sc = 1.0f;
    float y = __frcp_rn(sc);
    ull scn = dup2(-sc), yp = dup2(y), scp = dup2(sc);
    #pragma unroll
    for (int j=0;j<12;j++) {
        ull q = divm2(pk2(v[2*j], v[2*j+1]), scn, yp);
        float2 f = up2(q);
        float r0 = fminf(fmaxf(rintf(f.x), -127.0f), 127.0f);
        float r1 = fminf(fmaxf(rintf(f.y), -127.0f), 127.0f);
        float2 o = up2(fmul2(pk2(r0, r1), scp));
        v[2*j] = o.x; v[2*j+1] = o.y;
    }
}

// transposing block body: 8 rows quantized -> dstT[k][n0..n0+7], leading dim ldT
__device__ __forceinline__ void wrowT_block(const float* __restrict__ srcbase,
                                            float* __restrict__ dstT,
                                            int n0, int ldT) {
    __shared__ float S[8][772];
    int t = threadIdx.x, w = t >> 5, lane = t & 31;
    float v[24];
    wrow_calc(srcbase + (size_t)(n0 + w)*HIDDEN, v, lane);
    #pragma unroll
    for (int j=0;j<6;j++) *(float4*)&S[w][j*128 + lane*4] = *(float4*)&v[j*4];
    __syncthreads();
    #pragma unroll
    for (int i = 0; i < 6; ++i) {
        int c = t + i*256;                 // 0..1535
        int k = c >> 1, half = (c & 1) * 4;
        float4 o;
        o.x = S[half+0][k]; o.y = S[half+1][k];
        o.z = S[half+2][k]; o.w = S[half+3][k];
        *(float4*)&dstT[(size_t)k*ldT + n0 + half] = o;
    }
}

// normal (row-major) body
__device__ __forceinline__ void wrow_body(const float* __restrict__ x,
                                          float* __restrict__ d, int lane) {
    float v[24];
    wrow_calc(x, v, lane);
    #pragma unroll
    for (int j=0;j<6;j++) *(float4*)&d[j*128 + lane*4] = *(float4*)&v[j*4];
}

// activations -> XdT (4096 rows -> columns)
__global__ void __launch_bounds__(256) wrq_actT(const float* __restrict__ x,
                                                float* __restrict__ xdT) {
    wrowT_block(x, xdT, blockIdx.x*8, ROWS);
}
// Wq + Wk -> WdT mats 0,1 (transposed)
__global__ void __launch_bounds__(256) wrq_w1T(const float* __restrict__ wq,
                                               const float* __restrict__ wk,
                                               float* __restrict__ wdT) {
    int rowg = blockIdx.x * 8;
    if (rowg < 768) wrowT_block(wq, wdT, rowg, HIDDEN);
    else            wrowT_block(wk, wdT + (size_t)HIDDEN*HIDDEN, rowg - 768, HIDDEN);
}
// Wv -> WdT mat 2 (transposed); Wo -> Wod (row-major)
__global__ void __launch_bounds__(256) wrq_w2T(const float* __restrict__ wv,
                                               const float* __restrict__ wo,
                                               float* __restrict__ wdT2,
                                               float* __restrict__ wod) {
    int rowg = blockIdx.x * 8;
    if (rowg < 768) {
        wrowT_block(wv, wdT2, rowg, HIDDEN);
    } else {
        int r = rowg - 768 + (threadIdx.x >> 5);
        wrow_body(wo + (size_t)r*HIDDEN, wod + (size_t)r*HIDDEN, threadIdx.x & 31);
    }
}

__global__ void __launch_bounds__(256) wrowquant_one(const float* __restrict__ src,
                                                     float* __restrict__ dst) {
    int row = blockIdx.x*8 + (threadIdx.x>>5);
    int lane = threadIdx.x & 31;
    wrow_body(src + (size_t)row*HIDDEN, dst + (size_t)row*HIDDEN, lane);
}

// ---------------- QKV GEMM 256x128, 3-stage cp.async ring (1 sync/iter), FFMA2 ----------------
#define QKV_APAD 260
#define QKV_BPAD 132
#define QKV_STG (16*QKV_APAD + 16*QKV_BPAD)            // floats per stage
#define QKV_SMEM (3*QKV_STG*4)                         // 75264
__global__ void __launch_bounds__(256,1) gemmQKV(const float* __restrict__ AT,
                                                 const float* __restrict__ BT,
                                                 const float* __restrict__ b0,
                                                 const float* __restrict__ b1,
                                                 const float* __restrict__ b2,
                                                 float* __restrict__ Qd,
                                                 float* __restrict__ Kd,
                                                 float* __restrict__ Vd) {
    extern __shared__ float sm[];
    int t = threadIdx.x;
    int m0 = blockIdx.y * 256;
    int n0 = blockIdx.x * 128;
    int w = t >> 5, lane = t & 31;
    int wm = w & 3, wn = w >> 2;
    int lm = lane & 3, ln = lane >> 2;

    int tsel = n0 / 768;
    int nrel = n0 % 768;
    const float* Bt = BT + (size_t)tsel*HIDDEN*HIDDEN + nrel;

    ull acc[8][8];
    #pragma unroll
    for (int p=0;p<8;p++)
        #pragma unroll
        for (int j=0;j<8;j++) acc[p][j]=0ULL;

    int arA = t >> 6, acA = (t & 63) * 4;
    int arB = t >> 5, acB = (t & 31) * 4;
    #define Q_CPA(kt, stg) do { \
        float* Ab = sm + (stg)*QKV_STG; \
        float* Bb = Ab + 16*QKV_APAD; \
        _Pragma("unroll") \
        for (int l=0;l<4;l++) { \
            int r = arA + l*4; \
            cpa16(&Ab[r*QKV_APAD + acA], &AT[(size_t)((kt)*16 + r)*ROWS + m0 + acA]); \
        } \
        _Pragma("unroll") \
        for (int l=0;l<2;l++) { \
            int r = arB + l*8; \
            cpa16(&Bb[r*QKV_BPAD + acB], &Bt[(size_t)((kt)*16 + r)*HIDDEN + acB]); \
        } \
        asm volatile("cp.async.commit_group;"); \
    } while(0)

    Q_CPA(0, 0);
    Q_CPA(1, 1);

    int aull = wm*32 + lm*8;
    int boff = wn*64 + ln*8;
    int stg = 0;
    for (int kt = 0; kt < 48; ++kt) {
        if (kt < 46) asm volatile("cp.async.wait_group 1;");
        else         asm volatile("cp.async.wait_group 0;");
        __syncthreads();
        // issue stage kt+2 now: its buffer was consumed at kt-1, barrier above drained all readers
        if (kt < 46) {
            int nstg = stg + 2; if (nstg >= 3) nstg -= 3;
            Q_CPA(kt+2, nstg);
        }
        const float* Ab = sm + stg*QKV_STG;
        const float* Bb = Ab + 16*QKV_APAD;
        #pragma unroll
        for (int k = 0; k < 16; ++k) {     // ascending k; fused fma per output
            const ull* Au = (const ull*)(Ab + k*QKV_APAD);
            ulonglong2 a0 = *(const ulonglong2*)&Au[aull];
            ulonglong2 a1 = *(const ulonglong2*)&Au[aull+2];
            ulonglong2 a2 = *(const ulonglong2*)&Au[aull+4];
            ulonglong2 a3 = *(const ulonglong2*)&Au[aull+6];
            ull am[8] = {a0.x,a0.y,a1.x,a1.y,a2.x,a2.y,a3.x,a3.y};
            const float* Brow = Bb + k*QKV_BPAD + boff;
            float4 bl = *(const float4*)Brow;
            float4 bh = *(const float4*)(Brow+4);
            ull bd[8];
            bd[0]=dup2(bl.x); bd[1]=dup2(bl.y); bd[2]=dup2(bl.z); bd[3]=dup2(bl.w);
            bd[4]=dup2(bh.x); bd[5]=dup2(bh.y); bd[6]=dup2(bh.z); bd[7]=dup2(bh.w);
            #pragma unroll
            for (int p=0;p<8;p++)
                #pragma unroll
                for (int j=0;j<8;j++)
                    acc[p][j] = ffma2(am[p], bd[j], acc[p][j]);
        }
        if (++stg == 3) stg = 0;
    }

    // epilogue: bias + per-head (64) quantize -> Qd/Kd/Vd
    const float* bias = (tsel==0) ? b0 : (tsel==1 ? b1 : b2);
    float* dstbase = (tsel==0) ? Qd : (tsel==1 ? Kd : Vd);
    int hh = (nrel >> 6) + wn;
    int cb = nrel + wn*64 + ln*8;
    #pragma unroll
    for (int p=0;p<8;p++) {
        float ve[8], vo[8];
        #pragma unroll
        for (int j=0;j<8;j++) {
            float2 f = up2(acc[p][j]);
            ve[j] = __fadd_rn(f.x, bias[cb+j]);
            vo[j] = __fadd_rn(f.y, bias[cb+j]);
        }
        #pragma unroll
        for (int half=0; half<2; ++half) {
            float* v = half ? vo : ve;
            int gm = m0 + wm*64 + lm*16 + 2*p + half;
            float mxv = fabsf(v[0]);
            #pragma unroll
            for (int j=1;j<8;j++) mxv = fmaxf(mxv, fabsf(v[j]));
            mxv = fmaxf(mxv, __shfl_xor_sync(0xffffffffu, mxv, 4));
            mxv = fmaxf(mxv, __shfl_xor_sync(0xffffffffu, mxv, 8));
            mxv = fmaxf(mxv, __shfl_xor_sync(0xffffffffu, mxv, 16));
            float sc = __fdiv_rn(mxv, 127.0f);
            if (sc == 0.0f) sc = 1.0f;
            float y = __frcp_rn(sc);
            float q[8];
            #pragma unroll
            for (int j=0;j<8;j++)
                q[j] = __fmul_rn(fminf(fmaxf(rintf(divm(v[j], sc, y)), -127.0f), 127.0f), sc);
            int b = gm >> 9, s = gm & 511;
            float* drow = dstbase + ((size_t)((b*NHEADS + hh)*SS + s))*HDIM + ln*8;
            *(float4*)drow       = make_float4(q[0],q[1],q[2],q[3]);
            *(float4*)(drow + 4) = make_float4(q[4],q[5],q[6],q[7]);
        }
    }
}

// ---------------- out projection GEMM 64x128, 8m x 4n per thread, 3 CTAs/SM ----------------
#define GPAD 136
__global__ void __launch_bounds__(256,3) gemmOut(const float* __restrict__ A,
                                                 const float* __restrict__ B,
                                                 const float* __restrict__ b0,
                                                 float* __restrict__ C) {
    __shared__ __align__(16) float As[2*16*72];
    __shared__ __align__(16) float Bs[2*16*GPAD];
    int t = threadIdx.x;
    int m0 = blockIdx.y * 64;
    int n0 = blockIdx.x * 128;
    int w = t >> 5, lane = t & 31;
    int wm = w & 1, wn = w >> 1;
    int lm = lane & 3, ln = lane >> 2;
    int ar4 = t >> 2, ac4 = t & 3;

    ull acc2[4][4];
    #pragma unroll
    for (int p=0;p<4;p++)
        #pragma unroll
        for (int j=0;j<4;j++) acc2[p][j]=0ULL;

    float4 pa0, pb0, pb1;
    #define O_LDG(kt) do { \
        pa0 = *(const float4*)(A + (size_t)(m0 + ar4)*HIDDEN + (kt)*16 + ac4*4); \
        const float* Bp = B + (size_t)(n0+ar4)*HIDDEN + (kt)*16 + ac4*4; \
        pb0 = *(const float4*)Bp; \
        pb1 = *(const float4*)(Bp + (size_t)64*HIDDEN); \
    } while(0)
    #define O_STS(buf) do { \
        float* Ab = As + (buf)*16*72; \
        float* Bb = Bs + (buf)*16*GPAD; \
        Ab[(ac4*4+0)*72 + ar4] = pa0.x; Ab[(ac4*4+1)*72 + ar4] = pa0.y; \
        Ab[(ac4*4+2)*72 + ar4] = pa0.z; Ab[(ac4*4+3)*72 + ar4] = pa0.w; \
        Bb[(ac4*4+0)*GPAD + ar4] = pb0.x; Bb[(ac4*4+1)*GPAD + ar4] = pb0.y; \
        Bb[(ac4*4+2)*GPAD + ar4] = pb0.z; Bb[(ac4*4+3)*GPAD + ar4] = pb0.w; \
        Bb[(ac4*4+0)*GPAD + ar4+64] = pb1.x; Bb[(ac4*4+1)*GPAD + ar4+64] = pb1.y; \
        Bb[(ac4*4+2)*GPAD + ar4+64] = pb1.z; Bb[(ac4*4+3)*GPAD + ar4+64] = pb1.w; \
    } while(0)

    O_LDG(0);
    O_STS(0);
    __syncthreads();

    int aull = wm*16 + lm*4;
    int boff = wn*32 + ln*4;
    for (int kt = 0; kt < 48; ++kt) {
        int buf = kt & 1;
        if (kt < 47) O_LDG(kt+1);
        const float* Ab = As + buf*16*72;
        const float* Bb = Bs + buf*16*GPAD;
        #pragma unroll
        for (int k = 0; k < 16; ++k) {     // ascending k; fused fma per output
            const ull* Arow = (const ull*)(Ab + k*72);
            ulonglong2 aA = *(const ulonglong2*)&Arow[aull];
            ulonglong2 aB = *(const ulonglong2*)&Arow[aull+2];
            ull am[4] = {aA.x, aA.y, aB.x, aB.y};
            float4 bl = *(const float4*)(Bb + k*GPAD + boff);
            ull bd[4];
            bd[0]=dup2(bl.x); bd[1]=dup2(bl.y); bd[2]=dup2(bl.z); bd[3]=dup2(bl.w);
            #pragma unroll
            for (int p=0;p<4;p++)
                #pragma unroll
                for (int j=0;j<4;j++)
                    acc2[p][j] = ffma2(am[p], bd[j], acc2[p][j]);
        }
        if (kt < 47) {
            __syncthreads();
            O_STS(buf ^ 1);
            __syncthreads();
        }
    }

    int cb = n0 + wn*32 + ln*4;
    #pragma unroll
    for (int p=0;p<4;p++) {
        float ve[4], vo[4];
        #pragma unroll
        for (int j=0;j<4;j++) {
            float2 f = up2(acc2[p][j]);
            ve[j] = __fadd_rn(f.x, b0[cb+j]);
            vo[j] = __fadd_rn(f.y, b0[cb+j]);
        }
        int gm = m0 + wm*32 + lm*8 + 2*p;
        *(float4*)(C + (size_t)gm*768 + cb)     = make_float4(ve[0],ve[1],ve[2],ve[3]);
        *(float4*)(C + (size_t)(gm+1)*768 + cb) = make_float4(vo[0],vo[1],vo[2],vo[3]);
    }
}

// ---------------- attention scores GEMM: S[m,n] = (q[m,:].k[n,:]) * 0.125 -> g_P ----------------
#define SC_SMEM (2*64*128*4)   // 65536
__global__ void __launch_bounds__(256,2) attnSc() {
    extern __shared__ float sm[];
    float* Qs = sm;            // [d 64][m 128]
    float* Ks = sm + 64*128;   // [d 64][n 128]
    int t = threadIdx.x;
    int bh = blockIdx.x;
    int m0 = (blockIdx.y & 3) * 128;
    int n0 = (blockIdx.y >> 2) * 128;
    int w = t >> 5, lane = t & 31;
    int wm = w & 3, wn = w >> 2;
    int lm = lane & 3, ln = lane >> 2;

    {
        int r = t & 127, d0 = (t >> 7) * 32;
        const float* Qg = g_Qd + ((size_t)bh*SS + m0 + r)*HDIM + d0;
        const float* Kg = g_Kd + ((size_t)bh*SS + n0 + r)*HDIM + d0;
        #pragma unroll
        for (int j=0;j<8;j++) {
            float4 q = *(const float4*)(Qg + j*4);
            Qs[(d0+j*4+0)*128 + r] = q.x; Qs[(d0+j*4+1)*128 + r] = q.y;
            Qs[(d0+j*4+2)*128 + r] = q.z; Qs[(d0+j*4+3)*128 + r] = q.w;
            float4 k = *(const float4*)(Kg + j*4);
            Ks[(d0+j*4+0)*128 + r] = k.x; Ks[(d0+j*4+1)*128 + r] = k.y;
            Ks[(d0+j*4+2)*128 + r] = k.z; Ks[(d0+j*4+3)*128 + r] = k.w;
        }
    }
    __syncthreads();

    ull acc[4][8];
    #pragma unroll
    for (int p=0;p<4;p++)
        #pragma unroll
        for (int j=0;j<8;j++) acc[p][j]=0ULL;

    int aull = wm*16 + lm*4;
    int boff = wn*64 + ln*8;
    #pragma unroll 8
    for (int d = 0; d < 64; ++d) {
        const ull* Au = (const ull*)(Qs + d*128);
        ulonglong2 a0 = *(const ulonglong2*)&Au[aull];
        ulonglong2 a1 = *(const ulonglong2*)&Au[aull+2];
        ull am[4] = {a0.x, a0.y, a1.x, a1.y};
        const float* Brow = Ks + d*128 + boff;
        float4 bl = *(const float4*)Brow;
        float4 bh = *(const float4*)(Brow+4);
        ull bd[8];
        bd[0]=dup2(bl.x); bd[1]=dup2(bl.y); bd[2]=dup2(bl.z); bd[3]=dup2(bl.w);
        bd[4]=dup2(bh.x); bd[5]=dup2(bh.y); bd[6]=dup2(bh.z); bd[7]=dup2(bh.w);
        #pragma unroll
        for (int p=0;p<4;p++)
            #pragma unroll
            for (int j=0;j<8;j++)
                acc[p][j] = ffma2(am[p], bd[j], acc[p][j]);
    }

    int cb = n0 + wn*64 + ln*8;
    #pragma unroll
    for (int p=0;p<4;p++) {
        float ve[8], vo[8];
        #pragma unroll
        for (int j=0;j<8;j++) {
            float2 f = up2(acc[p][j]);
            ve[j] = __fmul_rn(f.x, 0.125f);
            vo[j] = __fmul_rn(f.y, 0.125f);
        }
        int gm = m0 + wm*32 + lm*8 + 2*p;
        float* se = g_P + ((size_t)bh*SS + gm)*SS + cb;
        float* so = g_P + ((size_t)bh*SS + gm + 1)*SS + cb;
        *(float4*)se     = make_float4(ve[0],ve[1],ve[2],ve[3]);
        *(float4*)(se+4) = make_float4(ve[4],ve[5],ve[6],ve[7]);
        *(float4*)so     = make_float4(vo[0],vo[1],vo[2],vo[3]);
        *(float4*)(so+4) = make_float4(vo[4],vo[5],vo[6],vo[7]);
    }
}

// ---------------- softmax (in-place on g_P): 4 rows per warp, batched strict sums ----------------
__global__ void __launch_bounds__(256) smx(PLA pla) {
    __shared__ float eb[8][4][512];
    __shared__ float2 sm_mc[12];
    __shared__ float2 sm_iv2[12];
    int t = threadIdx.x, w = t >> 5, lane = t & 31;
    if (t < 12) {
        sm_mc[t]  = make_float2(pla.m[t], pla.c[t]);
        sm_iv2[t] = make_float2(pla.iv[t], pla.iv[t+1]);
    }
    __syncthreads();
    int bh = blockIdx.x;
    int rowbase = blockIdx.y*32 + w*4;
    float amax[4];

    for (int r4 = 0; r4 < 4; ++r4) {
        const float* row = g_P + ((size_t)bh*SS + rowbase + r4)*SS;
        float v[16];
        #pragma unroll
        for (int j=0;j<4;j++) *(float4*)&v[j*4] = *(const float4*)&row[j*128 + lane*4];
        float mx = v[0];
        #pragma unroll
        for (int j=1;j<16;j++) mx = fmaxf(mx, v[j]);
        #pragma unroll
        for (int o=16;o>0;o>>=1) mx = fmaxf(mx, __shfl_xor_sync(0xffffffffu, mx, o));
        float am = 0.0f;
        #pragma unroll
        for (int j = 0; j < 16; j++) {
            float sh = __fadd_rn(v[j], -mx);
            float fr = rintf(__fmul_rn(sh, 67108864.0f));
            float fx = __fmul_rn(fr, 1.4901161193847656e-8f);
            float xc = fmaxf(fx, -10.0f);
            int idx = (int)floorf(__fmul_rn(__fadd_rn(xc, 10.0f), 1.2f));
            idx = idx < 0 ? 0 : (idx > 11 ? 11 : idx);
            float2 bnd = sm_iv2[idx];
            if (idx > 0 && xc < bnd.x) idx--;
            else if (idx < 11 && xc >= bnd.y) idx++;
            float2 mc = sm_mc[idx];
            float e = __fadd_rn(__fmul_rn(mc.x, xc), mc.y);
            v[j] = e;
            am = fmaxf(am, fabsf(e));
        }
        #pragma unroll
        for (int j=0;j<4;j++) *(float4*)&eb[w][r4][j*128 + lane*4] = *(float4*)&v[j*4];
        #pragma unroll
        for (int o=16;o>0;o>>=1) am = fmaxf(am, __shfl_xor_sync(0xffffffffu, am, o));
        amax[r4] = am;
    }
    __syncwarp();

    float ssum = 0.0f;
    if (lane < 4) {
        const float* er = eb[w][lane];
        #pragma unroll 8
        for (int i = 0; i < 512; i++) ssum = __fadd_rn(ssum, er[i]);
    }
    __syncwarp();

    for (int r4 = 0; r4 < 4; ++r4) {
        float denom = __fadd_rn(__shfl_sync(0xffffffffu, ssum, r4), 1e-9f);
        float yd = __frcp_rn(denom);
        ull dnp = dup2(-denom), ydp = dup2(yd);
        float qmx = divm(amax[r4], denom, yd);
        float sp = __fdiv_rn(qmx, 127.0f);
        if (sp == 0.0f) sp = 1.0f;
        float ys = __frcp_rn(sp);
        ull spn = dup2(-sp), ysp = dup2(ys), spp = dup2(sp);
        float* row = g_P + ((size_t)bh*SS + rowbase + r4)*SS;
        const float* er = eb[w][r4];
        #pragma unroll
        for (int j = 0; j < 4; ++j) {
            float4 e4 = *(const float4*)&er[j*128 + lane*4];
            ull pva = divm2(pk2(e4.x, e4.y), dnp, ydp);
            ull pvb = divm2(pk2(e4.z, e4.w), dnp, ydp);
            float2 fa = up2(divm2(pva, spn, ysp));
            float2 fb = up2(divm2(pvb, spn, ysp));
            float r0 = fminf(fmaxf(rintf(fa.x), -127.0f), 127.0f);
            float r1 = fminf(fmaxf(rintf(fa.y), -127.0f), 127.0f);
            float r2 = fminf(fmaxf(rintf(fb.x), -127.0f), 127.0f);
            float r3 = fminf(fmaxf(rintf(fb.y), -127.0f), 127.0f);
            ulonglong2 o;
            o.x = fmul2(pk2(r0, r1), spp);
            o.y = fmul2(pk2(r2, r3), spp);
            *(ulonglong2*)&row[j*128 + lane*4] = o;
        }
    }
}

// ---------------- attention P@V: fp32 P from gmem, single-buffer 32KB V chunks ----------------
#define PV_SMEM (128*64*4)   // 32768
__global__ void __launch_bounds__(256) attnPV() {
    extern __shared__ float Vs[];
    int t = threadIdx.x;
    int tx = t & 7, ty = t >> 3;
    int bh = blockIdx.x;
    int m0 = blockIdx.y * 128;

    const float* Vg = g_Vd + (size_t)bh*SS*HDIM;

    ull acc[4][4];
    #pragma unroll
    for (int i=0;i<4;i++)
        #pragma unroll
        for (int u=0;u<4;u++) acc[i][u]=0ULL;

    const float* Pg = g_P + ((size_t)bh*SS + m0 + ty*4)*SS;
    for (int kc = 0; kc < 4; ++kc) {
        if (kc > 0) __syncthreads();
        #pragma unroll
        for (int l=0;l<8;l++)
            *(float4*)&Vs[l*1024 + t*4] = *(const float4*)(Vg + kc*8192 + l*1024 + t*4);
        __syncthreads();
        const ull* Vu = (const ull*)Vs;
        #pragma unroll 4
        for (int kb = 0; kb < 32; ++kb) {
            float pa[4][4];
            #pragma unroll
            for (int i=0;i<4;i++)
                *(float4*)pa[i] = *(const float4*)&Pg[(size_t)i*SS + kc*128 + kb*4];
            #pragma unroll
            for (int kk = 0; kk < 4; ++kk) {
                int k = kb*4 + kk;
                ulonglong2 v0 = *(const ulonglong2*)&Vu[k*32 + tx*4];
                ulonglong2 v1 = *(const ulonglong2*)&Vu[k*32 + tx*4 + 2];
                ull vp[4] = {v0.x, v0.y, v1.x, v1.y};
                #pragma unroll
                for (int i=0;i<4;i++) {
                    ull pd = dup2(pa[i][kk]);
                    acc[i][0] = ffma2(pd, vp[0], acc[i][0]);
                    acc[i][1] = ffma2(pd, vp[1], acc[i][1]);
                    acc[i][2] = ffma2(pd, vp[2], acc[i][2]);
                    acc[i][3] = ffma2(pd, vp[3], acc[i][3]);
                }
            }
        }
    }
    int b = bh / NHEADS, h = bh % NHEADS;
    #pragma unroll
    for (int i=0;i<4;i++) {
        int s = m0 + ty*4 + i;
        float* Co = g_CTX + ((size_t)(b*SS + s))*HIDDEN + h*HDIM + tx*8;
        float2 f0 = up2(acc[i][0]), f1 = up2(acc[i][1]);
        float2 f2 = up2(acc[i][2]), f3 = up2(acc[i][3]);
        *(float4*)Co     = make_float4(f0.x, f0.y, f1.x, f1.y);
        *(float4*)(Co+4) = make_float4(f2.x, f2.y, f3.x, f3.y);
    }
}

// ---------------- host: replicate np.polyfit coefficients in double ----------------
static void build_pla(PLA& p) {
    double xs[1001], ys[1001];
    double step = 10.0 / 1000.0;
    for (int j = 0; j <= 1000; j++) xs[j] = -10.0 + (double)j * step;
    xs[1000] = 0.0;
    for (int j = 0; j <= 1000; j++) ys[j] = exp(xs[j]);
    double iv[13];
    double st2 = 10.0 / 12.0;
    for (int i = 0; i < 13; i++) iv[i] = -10.0 + (double)i * st2;
    iv[12] = 0.0;
    for (int i = 0; i < 12; i++) {
        double a = iv[i], b = iv[i+1];
        double n = 0, Sx = 0, Sy = 0, Sxx = 0, Sxy = 0;
        for (int j = 0; j <= 1000; j++) {
            if (xs[j] >= a && xs[j] <= b) {
                n += 1.0; Sx += xs[j]; Sy += ys[j];
                Sxx += xs[j]*xs[j]; Sxy += xs[j]*ys[j];
            }
        }
        double m = (n*Sxy - Sx*Sy) / (n*Sxx - Sx*Sx);
        double c = (Sy - m*Sx) / n;
        p.m[i] = (float)m;
        p.c[i] = (float)c;
    }
    for (int i = 0; i < 13; i++) p.iv[i] = (float)iv[i];
}

extern "C" void kernel_launch(void* const* d_in, const int* in_sizes, int n_in,
                              void* d_out, int out_size) {
    (void)in_sizes; (void)n_in; (void)out_size;
    const float* hs = (const float*)d_in[0];
    const float* Wq = (const float*)d_in[1];
    const float* bq = (const float*)d_in[2];
    const float* Wk = (const float*)d_in[3];
    const float* bk = (const float*)d_in[4];
    const float* Wv = (const float*)d_in[5];
    const float* bv = (const float*)d_in[6];
    const float* Wo = (const float*)d_in[7];
    const float* bo = (const float*)d_in[8];

    void *pXdT, *pWdT, *pWod, *pCTX, *pCd, *pQd, *pKd, *pVd;
    cudaGetSymbolAddress(&pXdT, g_XdT);
    cudaGetSymbolAddress(&pWdT, g_WdT);
    cudaGetSymbolAddress(&pWod, g_Wod);
    cudaGetSymbolAddress(&pCTX, g_CTX);
    cudaGetSymbolAddress(&pCd, g_Cd);
    cudaGetSymbolAddress(&pQd, g_Qd);
    cudaGetSymbolAddress(&pKd, g_Kd);
    cudaGetSymbolAddress(&pVd, g_Vd);

    PLA pla;
    build_pla(pla);

    // 1) fake-quant with transposed (k-major) outputs for the QKV GEMM operands
    wrq_actT<<<512, 256>>>(hs, (float*)pXdT);
    wrq_w1T<<<192, 256>>>(Wq, Wk, (float*)pWdT);
    wrq_w2T<<<192, 256>>>(Wv, Wo, (float*)pWdT + (size_t)2*HIDDEN*HIDDEN, (float*)pWod);

    // 2) QKV projection (3-stage cp.async FFMA2 GEMM) + per-head quantize  [launch #4]
    cudaFuncSetAttribute(gemmQKV, cudaFuncAttributeMaxDynamicSharedMemorySize, QKV_SMEM);
    gemmQKV<<<dim3(18, 16), 256, QKV_SMEM>>>((const float*)pXdT, (const float*)pWdT,
                                             bq, bk, bv,
                                             (float*)pQd, (float*)pKd, (float*)pVd);

    // 3) scores GEMM -> g_P ; softmax in place (4 rows/warp) ; P@V
    cudaFuncSetAttribute(attnSc, cudaFuncAttributeMaxDynamicSharedMemorySize, SC_SMEM);
    attnSc<<<dim3(96, 16), 256, SC_SMEM>>>();
    smx<<<dim3(96, 16), 256>>>(pla);
    cudaFuncSetAttribute(attnPV, cudaFuncAttributeMaxDynamicSharedMemorySize, PV_SMEM);
    attnPV<<<dim3(96, 4), 256, PV_SMEM>>>();

    // 4) fake-quant ctx rows + output projection
    wrowquant_one<<<512, 256>>>((const float*)pCTX, (float*)pCd);
    gemmOut<<<dim3(6, 64), 256>>>((const float*)pCd, (const float*)pWod, bo, (float*)d_out);
}

// round 15
// speedup vs baseline: 1.0283x; 1.0283x over previous
#include <cuda_runtime.h>
#include <cstdint>
#include <cmath>

#define HIDDEN 768
#define NHEADS 12
#define HDIM 64
#define BB 8
#define SS 512
#define ROWS (BB*SS)              // 4096
#define HEADROWS (BB*NHEADS*SS)   // 49152

// ---------------- scratch (static device allocations; no cudaMalloc) ----------------
__device__ float g_XdT[(size_t)HIDDEN*ROWS];       // dequant hidden_states, TRANSPOSED [k][m]
__device__ float g_WdT[(size_t)3*HIDDEN*HIDDEN];   // dequant Wq|Wk|Wv, each TRANSPOSED [k][n]
__device__ float g_Wod[(size_t)HIDDEN*HIDDEN];     // dequant Wo (row-major)
__device__ float g_Qd[(size_t)HEADROWS*HDIM];      // dequant per-head q
__device__ float g_Kd[(size_t)HEADROWS*HDIM];
__device__ float g_Vd[(size_t)HEADROWS*HDIM];
__device__ float g_P [(size_t)HEADROWS*SS];        // scores, then (in-place) dequant probs
__device__ float g_CTX[(size_t)ROWS*HIDDEN];
__device__ float g_Cd[(size_t)ROWS*HIDDEN];        // dequant quantized ctx (row-major)

struct PLA { float m[12]; float c[12]; float iv[13]; };

typedef unsigned long long ull;

// packed f32x2 ops: two independent IEEE RN ops in one instruction
__device__ __forceinline__ ull ffma2(ull a, ull b, ull c) {
    ull d;
    asm("fma.rn.f32x2 %0, %1, %2, %3;" : "=l"(d) : "l"(a), "l"(b), "l"(c));
    return d;
}
__device__ __forceinline__ ull fmul2(ull a, ull b) {
    ull d;
    asm("mul.rn.f32x2 %0, %1, %2;" : "=l"(d) : "l"(a), "l"(b));
    return d;
}
__device__ __forceinline__ float2 up2(ull v) {
    float2 r;
    asm("mov.b64 {%0, %1}, %2;" : "=f"(r.x), "=f"(r.y) : "l"(v));
    return r;
}
__device__ __forceinline__ ull dup2(float x) {
    ull d;
    asm("mov.b64 %0, {%1, %1};" : "=l"(d) : "f"(x));
    return d;
}
__device__ __forceinline__ ull pk2(float a, float b) {
    ull d;
    asm("mov.b64 %0, {%1, %2};" : "=l"(d) : "f"(a), "f"(b));
    return d;
}
// Markstein correctly-rounded division given y = __frcp_rn(d). Bit-identical to __fdiv_rn(v,d).
__device__ __forceinline__ float divm(float v, float d, float y) {
    float q0 = __fmul_rn(v, y);
    float r  = __fmaf_rn(-q0, d, v);
    return __fmaf_rn(r, y, q0);
}
// packed Markstein: dn = dup2(-d), yp = dup2(y). Per-lane bit-identical to divm.
__device__ __forceinline__ ull divm2(ull vp, ull dn, ull yp) {
    ull q0 = fmul2(vp, yp);
    ull r  = ffma2(q0, dn, vp);
    return ffma2(r, yp, q0);
}
// cp.async 16B gmem -> smem
__device__ __forceinline__ void cpa16(void* smp, const void* gmp) {
    unsigned s = (unsigned)__cvta_generic_to_shared(smp);
    asm volatile("cp.async.cg.shared.global [%0], [%1], 16;" :: "r"(s), "l"(gmp));
}

// ---------------- warp-per-row (768) quantize: compute v[24] in regs ----------------
__device__ __forceinline__ void wrow_calc(const float* __restrict__ x, float* v, int lane) {
    #pragma unroll
    for (int j=0;j<6;j++) *(float4*)&v[j*4] = *(const float4*)&x[j*128 + lane*4];
    float mx = fabsf(v[0]);
    #pragma unroll
    for (int j=1;j<24;j++) mx = fmaxf(mx, fabsf(v[j]));
    #pragma unroll
    for (int o=16;o>0;o>>=1) mx = fmaxf(mx, __shfl_xor_sync(0xffffffffu, mx, o));
    float sc = __fdiv_rn(mx, 127.0f);
    if (sc == 0.0f) sc = 1.0f;
    float y = __frcp_rn(sc);
    ull scn = dup2(-sc), yp = dup2(y), scp = dup2(sc);
    #pragma unroll
    for (int j=0;j<12;j++) {
        ull q = divm2(pk2(v[2*j], v[2*j+1]), scn, yp);
        float2 f = up2(q);
        float r0 = fminf(fmaxf(rintf(f.x), -127.0f), 127.0f);
        float r1 = fminf(fmaxf(rintf(f.y), -127.0f), 127.0f);
        float2 o = up2(fmul2(pk2(r0, r1), scp));
        v[2*j] = o.x; v[2*j+1] = o.y;
    }
}

// transposing block body: 8 rows quantized -> dstT[k][n0..n0+7], leading dim ldT
__device__ __forceinline__ void wrowT_block(const float* __restrict__ srcbase,
                                            float* __restrict__ dstT,
                                            int n0, int ldT) {
    __shared__ float S[8][772];
    int t = threadIdx.x, w = t >> 5, lane = t & 31;
    float v[24];
    wrow_calc(srcbase + (size_t)(n0 + w)*HIDDEN, v, lane);
    #pragma unroll
    for (int j=0;j<6;j++) *(float4*)&S[w][j*128 + lane*4] = *(float4*)&v[j*4];
    __syncthreads();
    #pragma unroll
    for (int i = 0; i < 6; ++i) {
        int c = t + i*256;                 // 0..1535
        int k = c >> 1, half = (c & 1) * 4;
        float4 o;
        o.x = S[half+0][k]; o.y = S[half+1][k];
        o.z = S[half+2][k]; o.w = S[half+3][k];
        *(float4*)&dstT[(size_t)k*ldT + n0 + half] = o;
    }
}

// normal (row-major) body
__device__ __forceinline__ void wrow_body(const float* __restrict__ x,
                                          float* __restrict__ d, int lane) {
    float v[24];
    wrow_calc(x, v, lane);
    #pragma unroll
    for (int j=0;j<6;j++) *(float4*)&d[j*128 + lane*4] = *(float4*)&v[j*4];
}

// activations -> XdT (4096 rows -> columns)
__global__ void __launch_bounds__(256) wrq_actT(const float* __restrict__ x,
                                                float* __restrict__ xdT) {
    wrowT_block(x, xdT, blockIdx.x*8, ROWS);
}
// Wq + Wk -> WdT mats 0,1 (transposed)
__global__ void __launch_bounds__(256) wrq_w1T(const float* __restrict__ wq,
                                               const float* __restrict__ wk,
                                               float* __restrict__ wdT) {
    int rowg = blockIdx.x * 8;
    if (rowg < 768) wrowT_block(wq, wdT, rowg, HIDDEN);
    else            wrowT_block(wk, wdT + (size_t)HIDDEN*HIDDEN, rowg - 768, HIDDEN);
}
// Wv -> WdT mat 2 (transposed); Wo -> Wod (row-major)
__global__ void __launch_bounds__(256) wrq_w2T(const float* __restrict__ wv,
                                               const float* __restrict__ wo,
                                               float* __restrict__ wdT2,
                                               float* __restrict__ wod) {
    int rowg = blockIdx.x * 8;
    if (rowg < 768) {
        wrowT_block(wv, wdT2, rowg, HIDDEN);
    } else {
        int r = rowg - 768 + (threadIdx.x >> 5);
        wrow_body(wo + (size_t)r*HIDDEN, wod + (size_t)r*HIDDEN, threadIdx.x & 31);
    }
}

__global__ void __launch_bounds__(256) wrowquant_one(const float* __restrict__ src,
                                                     float* __restrict__ dst) {
    int row = blockIdx.x*8 + (threadIdx.x>>5);
    int lane = threadIdx.x & 31;
    wrow_body(src + (size_t)row*HIDDEN, dst + (size_t)row*HIDDEN, lane);
}

// ---------------- QKV GEMM 128x128, 8m x 8n per thread, 2 CTAs/SM, 2-stage cp.async ----------------
#define QG_PAD 132
#define QG_STG (2*16*QG_PAD)                     // A+B floats per stage
#define QG_SMEM (2*QG_STG*4)                     // 33792 B
__global__ void __launch_bounds__(256,2) gemmQKV(const float* __restrict__ AT,
                                                 const float* __restrict__ BT,
                                                 const float* __restrict__ b0,
                                                 const float* __restrict__ b1,
                                                 const float* __restrict__ b2,
                                                 float* __restrict__ Qd,
                                                 float* __restrict__ Kd,
                                                 float* __restrict__ Vd) {
    extern __shared__ float sm[];
    int t = threadIdx.x;
    int m0 = blockIdx.y * 128;
    int n0 = blockIdx.x * 128;
    int w = t >> 5, lane = t & 31;
    int wm = w & 3, wn = w >> 2;           // warp tile: 32m x 64n
    int lm = lane & 3, ln = lane >> 2;     // lane tile: 8m x 8n
    int tsel = n0 / 768;
    int nrel = n0 % 768;
    const float* Bt = BT + (size_t)tsel*HIDDEN*HIDDEN + nrel;

    ull acc[4][8];
    #pragma unroll
    for (int p=0;p<4;p++)
        #pragma unroll
        for (int j=0;j<8;j++) acc[p][j]=0ULL;

    int ar = t >> 5, ac = (t & 31) * 4;    // 512 float4 per operand: rows ar + l*8
    #define QG_CPA(kt, stg) do { \
        float* Ab = sm + (stg)*QG_STG; \
        float* Bb = Ab + 16*QG_PAD; \
        _Pragma("unroll") \
        for (int l=0;l<2;l++) { \
            int r = ar + l*8; \
            cpa16(&Ab[r*QG_PAD + ac], &AT[(size_t)((kt)*16 + r)*ROWS + m0 + ac]); \
            cpa16(&Bb[r*QG_PAD + ac], &Bt[(size_t)((kt)*16 + r)*HIDDEN + ac]); \
        } \
        asm volatile("cp.async.commit_group;"); \
    } while(0)

    QG_CPA(0, 0);

    int aull = wm*16 + lm*4;               // ull offset within 128-m row (64 ulls)
    int boff = wn*64 + ln*8;
    for (int kt = 0; kt < 48; ++kt) {
        int buf = kt & 1;
        if (kt < 47) {
            QG_CPA(kt+1, buf ^ 1);
            asm volatile("cp.async.wait_group 1;");
        } else {
            asm volatile("cp.async.wait_group 0;");
        }
        __syncthreads();
        const float* Ab = sm + buf*QG_STG;
        const float* Bb = Ab + 16*QG_PAD;
        #pragma unroll
        for (int k = 0; k < 16; ++k) {     // ascending k; fused fma per output
            const ull* Au = (const ull*)(Ab + k*QG_PAD);
            ulonglong2 a0 = *(const ulonglong2*)&Au[aull];
            ulonglong2 a1 = *(const ulonglong2*)&Au[aull+2];
            ull am[4] = {a0.x, a0.y, a1.x, a1.y};
            const float* Brow = Bb + k*QG_PAD + boff;
            float4 bl = *(const float4*)Brow;
            float4 bh = *(const float4*)(Brow+4);
            ull bd[8];
            bd[0]=dup2(bl.x); bd[1]=dup2(bl.y); bd[2]=dup2(bl.z); bd[3]=dup2(bl.w);
            bd[4]=dup2(bh.x); bd[5]=dup2(bh.y); bd[6]=dup2(bh.z); bd[7]=dup2(bh.w);
            #pragma unroll
            for (int p=0;p<4;p++)
                #pragma unroll
                for (int j=0;j<8;j++)
                    acc[p][j] = ffma2(am[p], bd[j], acc[p][j]);
        }
        if (kt < 47) __syncthreads();
    }

    // epilogue: bias + per-head (64) quantize -> Qd/Kd/Vd
    const float* bias = (tsel==0) ? b0 : (tsel==1 ? b1 : b2);
    float* dstbase = (tsel==0) ? Qd : (tsel==1 ? Kd : Vd);
    int hh = (nrel >> 6) + wn;
    int cb = nrel + wn*64 + ln*8;
    #pragma unroll
    for (int p=0;p<4;p++) {
        float ve[8], vo[8];
        #pragma unroll
        for (int j=0;j<8;j++) {
            float2 f = up2(acc[p][j]);
            ve[j] = __fadd_rn(f.x, bias[cb+j]);
            vo[j] = __fadd_rn(f.y, bias[cb+j]);
        }
        #pragma unroll
        for (int half=0; half<2; ++half) {
            float* v = half ? vo : ve;
            int gm = m0 + wm*32 + lm*8 + 2*p + half;
            float mxv = fabsf(v[0]);
            #pragma unroll
            for (int j=1;j<8;j++) mxv = fmaxf(mxv, fabsf(v[j]));
            mxv = fmaxf(mxv, __shfl_xor_sync(0xffffffffu, mxv, 4));
            mxv = fmaxf(mxv, __shfl_xor_sync(0xffffffffu, mxv, 8));
            mxv = fmaxf(mxv, __shfl_xor_sync(0xffffffffu, mxv, 16));
            float sc = __fdiv_rn(mxv, 127.0f);
            if (sc == 0.0f) sc = 1.0f;
            float y = __frcp_rn(sc);
            float q[8];
            #pragma unroll
            for (int j=0;j<8;j++)
                q[j] = __fmul_rn(fminf(fmaxf(rintf(divm(v[j], sc, y)), -127.0f), 127.0f), sc);
            int b = gm >> 9, s = gm & 511;
            float* drow = dstbase + ((size_t)((b*NHEADS + hh)*SS + s))*HDIM + ln*8;
            *(float4*)drow       = make_float4(q[0],q[1],q[2],q[3]);
            *(float4*)(drow + 4) = make_float4(q[4],q[5],q[6],q[7]);
        }
    }
}

// ---------------- out projection GEMM 64x128, 8m x 4n per thread, 3 CTAs/SM ----------------
#define GPAD 136
__global__ void __launch_bounds__(256,3) gemmOut(const float* __restrict__ A,
                                                 const float* __restrict__ B,
                                                 const float* __restrict__ b0,
                                                 float* __restrict__ C) {
    __shared__ __align__(16) float As[2*16*72];
    __shared__ __align__(16) float Bs[2*16*GPAD];
    int t = threadIdx.x;
    int m0 = blockIdx.y * 64;
    int n0 = blockIdx.x * 128;
    int w = t >> 5, lane = t & 31;
    int wm = w & 1, wn = w >> 1;
    int lm = lane & 3, ln = lane >> 2;
    int ar4 = t >> 2, ac4 = t & 3;

    ull acc2[4][4];
    #pragma unroll
    for (int p=0;p<4;p++)
        #pragma unroll
        for (int j=0;j<4;j++) acc2[p][j]=0ULL;

    float4 pa0, pb0, pb1;
    #define O_LDG(kt) do { \
        pa0 = *(const float4*)(A + (size_t)(m0 + ar4)*HIDDEN + (kt)*16 + ac4*4); \
        const float* Bp = B + (size_t)(n0+ar4)*HIDDEN + (kt)*16 + ac4*4; \
        pb0 = *(const float4*)Bp; \
        pb1 = *(const float4*)(Bp + (size_t)64*HIDDEN); \
    } while(0)
    #define O_STS(buf) do { \
        float* Ab = As + (buf)*16*72; \
        float* Bb = Bs + (buf)*16*GPAD; \
        Ab[(ac4*4+0)*72 + ar4] = pa0.x; Ab[(ac4*4+1)*72 + ar4] = pa0.y; \
        Ab[(ac4*4+2)*72 + ar4] = pa0.z; Ab[(ac4*4+3)*72 + ar4] = pa0.w; \
        Bb[(ac4*4+0)*GPAD + ar4] = pb0.x; Bb[(ac4*4+1)*GPAD + ar4] = pb0.y; \
        Bb[(ac4*4+2)*GPAD + ar4] = pb0.z; Bb[(ac4*4+3)*GPAD + ar4] = pb0.w; \
        Bb[(ac4*4+0)*GPAD + ar4+64] = pb1.x; Bb[(ac4*4+1)*GPAD + ar4+64] = pb1.y; \
        Bb[(ac4*4+2)*GPAD + ar4+64] = pb1.z; Bb[(ac4*4+3)*GPAD + ar4+64] = pb1.w; \
    } while(0)

    O_LDG(0);
    O_STS(0);
    __syncthreads();

    int aull = wm*16 + lm*4;
    int boff = wn*32 + ln*4;
    for (int kt = 0; kt < 48; ++kt) {
        int buf = kt & 1;
        if (kt < 47) O_LDG(kt+1);
        const float* Ab = As + buf*16*72;
        const float* Bb = Bs + buf*16*GPAD;
        #pragma unroll
        for (int k = 0; k < 16; ++k) {     // ascending k; fused fma per output
            const ull* Arow = (const ull*)(Ab + k*72);
            ulonglong2 aA = *(const ulonglong2*)&Arow[aull];
            ulonglong2 aB = *(const ulonglong2*)&Arow[aull+2];
            ull am[4] = {aA.x, aA.y, aB.x, aB.y};
            float4 bl = *(const float4*)(Bb + k*GPAD + boff);
            ull bd[4];
            bd[0]=dup2(bl.x); bd[1]=dup2(bl.y); bd[2]=dup2(bl.z); bd[3]=dup2(bl.w);
            #pragma unroll
            for (int p=0;p<4;p++)
                #pragma unroll
                for (int j=0;j<4;j++)
                    acc2[p][j] = ffma2(am[p], bd[j], acc2[p][j]);
        }
        if (kt < 47) {
            __syncthreads();
            O_STS(buf ^ 1);
            __syncthreads();
        }
    }

    int cb = n0 + wn*32 + ln*4;
    #pragma unroll
    for (int p=0;p<4;p++) {
        float ve[4], vo[4];
        #pragma unroll
        for (int j=0;j<4;j++) {
            float2 f = up2(acc2[p][j]);
            ve[j] = __fadd_rn(f.x, b0[cb+j]);
            vo[j] = __fadd_rn(f.y, b0[cb+j]);
        }
        int gm = m0 + wm*32 + lm*8 + 2*p;
        *(float4*)(C + (size_t)gm*768 + cb)     = make_float4(ve[0],ve[1],ve[2],ve[3]);
        *(float4*)(C + (size_t)(gm+1)*768 + cb) = make_float4(vo[0],vo[1],vo[2],vo[3]);
    }
}

// ---------------- attention scores GEMM: S[m,n] = (q[m,:].k[n,:]) * 0.125 -> g_P ----------------
#define SC_SMEM (2*64*128*4)   // 65536
__global__ void __launch_bounds__(256,1) attnSc() {
    extern __shared__ float sm[];
    float* Qs = sm;            // [d 64][m 128]
    float* Ks = sm + 64*128;   // [d 64][n 128]
    int t = threadIdx.x;
    int bh = blockIdx.x;
    int m0 = (blockIdx.y & 3) * 128;
    int n0 = (blockIdx.y >> 2) * 128;
    int w = t >> 5, lane = t & 31;
    int wm = w & 3, wn = w >> 2;
    int lm = lane & 3, ln = lane >> 2;

    {
        int r = t & 127, d0 = (t >> 7) * 32;
        const float* Qg = g_Qd + ((size_t)bh*SS + m0 + r)*HDIM + d0;
        const float* Kg = g_Kd + ((size_t)bh*SS + n0 + r)*HDIM + d0;
        #pragma unroll
        for (int j=0;j<8;j++) {
            float4 q = *(const float4*)(Qg + j*4);
            Qs[(d0+j*4+0)*128 + r] = q.x; Qs[(d0+j*4+1)*128 + r] = q.y;
            Qs[(d0+j*4+2)*128 + r] = q.z; Qs[(d0+j*4+3)*128 + r] = q.w;
            float4 k = *(const float4*)(Kg + j*4);
            Ks[(d0+j*4+0)*128 + r] = k.x; Ks[(d0+j*4+1)*128 + r] = k.y;
            Ks[(d0+j*4+2)*128 + r] = k.z; Ks[(d0+j*4+3)*128 + r] = k.w;
        }
    }
    __syncthreads();

    ull acc[4][8];
    #pragma unroll
    for (int p=0;p<4;p++)
        #pragma unroll
        for (int j=0;j<8;j++) acc[p][j]=0ULL;

    int aull = wm*16 + lm*4;
    int boff = wn*64 + ln*8;
    #pragma unroll 8
    for (int d = 0; d < 64; ++d) {
        const ull* Au = (const ull*)(Qs + d*128);
        ulonglong2 a0 = *(const ulonglong2*)&Au[aull];
        ulonglong2 a1 = *(const ulonglong2*)&Au[aull+2];
        ull am[4] = {a0.x, a0.y, a1.x, a1.y};
        const float* Brow = Ks + d*128 + boff;
        float4 bl = *(const float4*)Brow;
        float4 bh = *(const float4*)(Brow+4);
        ull bd[8];
        bd[0]=dup2(bl.x); bd[1]=dup2(bl.y); bd[2]=dup2(bl.z); bd[3]=dup2(bl.w);
        bd[4]=dup2(bh.x); bd[5]=dup2(bh.y); bd[6]=dup2(bh.z); bd[7]=dup2(bh.w);
        #pragma unroll
        for (int p=0;p<4;p++)
            #pragma unroll
            for (int j=0;j<8;j++)
                acc[p][j] = ffma2(am[p], bd[j], acc[p][j]);
    }

    int cb = n0 + wn*64 + ln*8;
    #pragma unroll
    for (int p=0;p<4;p++) {
        float ve[8], vo[8];
        #pragma unroll
        for (int j=0;j<8;j++) {
            float2 f = up2(acc[p][j]);
            ve[j] = __fmul_rn(f.x, 0.125f);
            vo[j] = __fmul_rn(f.y, 0.125f);
        }
        int gm = m0 + wm*32 + lm*8 + 2*p;
        float* se = g_P + ((size_t)bh*SS + gm)*SS + cb;
        float* so = g_P + ((size_t)bh*SS + gm + 1)*SS + cb;
        *(float4*)se     = make_float4(ve[0],ve[1],ve[2],ve[3]);
        *(float4*)(se+4) = make_float4(ve[4],ve[5],ve[6],ve[7]);
        *(float4*)so     = make_float4(vo[0],vo[1],vo[2],vo[3]);
        *(float4*)(so+4) = make_float4(vo[4],vo[5],vo[6],vo[7]);
    }
}

// ---------------- softmax (in-place on g_P): 4 rows per warp, batched strict sums ----------------
__global__ void __launch_bounds__(256) smx(PLA pla) {
    __shared__ float eb[8][4][512];
    __shared__ float2 sm_mc[12];
    __shared__ float2 sm_iv2[12];
    int t = threadIdx.x, w = t >> 5, lane = t & 31;
    if (t < 12) {
        sm_mc[t]  = make_float2(pla.m[t], pla.c[t]);
        sm_iv2[t] = make_float2(pla.iv[t], pla.iv[t+1]);
    }
    __syncthreads();
    int bh = blockIdx.x;
    int rowbase = blockIdx.y*32 + w*4;
    float amax[4];

    for (int r4 = 0; r4 < 4; ++r4) {
        const float* row = g_P + ((size_t)bh*SS + rowbase + r4)*SS;
        float v[16];
        #pragma unroll
        for (int j=0;j<4;j++) *(float4*)&v[j*4] = *(const float4*)&row[j*128 + lane*4];
        float mx = v[0];
        #pragma unroll
        for (int j=1;j<16;j++) mx = fmaxf(mx, v[j]);
        #pragma unroll
        for (int o=16;o>0;o>>=1) mx = fmaxf(mx, __shfl_xor_sync(0xffffffffu, mx, o));
        float am = 0.0f;
        #pragma unroll
        for (int j = 0; j < 16; j++) {
            float sh = __fadd_rn(v[j], -mx);
            float fr = rintf(__fmul_rn(sh, 67108864.0f));
            float fx = __fmul_rn(fr, 1.4901161193847656e-8f);
            float xc = fmaxf(fx, -10.0f);
            int idx = (int)floorf(__fmul_rn(__fadd_rn(xc, 10.0f), 1.2f));
            idx = idx < 0 ? 0 : (idx > 11 ? 11 : idx);
            float2 bnd = sm_iv2[idx];
            if (idx > 0 && xc < bnd.x) idx--;
            else if (idx < 11 && xc >= bnd.y) idx++;
            float2 mc = sm_mc[idx];
            float e = __fadd_rn(__fmul_rn(mc.x, xc), mc.y);
            v[j] = e;
            am = fmaxf(am, fabsf(e));
        }
        #pragma unroll
        for (int j=0;j<4;j++) *(float4*)&eb[w][r4][j*128 + lane*4] = *(float4*)&v[j*4];
        #pragma unroll
        for (int o=16;o>0;o>>=1) am = fmaxf(am, __shfl_xor_sync(0xffffffffu, am, o));
        amax[r4] = am;
    }
    __syncwarp();

    float ssum = 0.0f;
    if (lane < 4) {
        const float* er = eb[w][lane];
        #pragma unroll 8
        for (int i = 0; i < 512; i++) ssum = __fadd_rn(ssum, er[i]);
    }
    __syncwarp();

    for (int r4 = 0; r4 < 4; ++r4) {
        float denom = __fadd_rn(__shfl_sync(0xffffffffu, ssum, r4), 1e-9f);
        float yd = __frcp_rn(denom);
        ull dnp = dup2(-denom), ydp = dup2(yd);
        float qmx = divm(amax[r4], denom, yd);
        float sp = __fdiv_rn(qmx, 127.0f);
        if (sp == 0.0f) sp = 1.0f;
        float ys = __frcp_rn(sp);
        ull spn = dup2(-sp), ysp = dup2(ys), spp = dup2(sp);
        float* row = g_P + ((size_t)bh*SS + rowbase + r4)*SS;
        const float* er = eb[w][r4];
        #pragma unroll
        for (int j = 0; j < 4; ++j) {
            float4 e4 = *(const float4*)&er[j*128 + lane*4];
            ull pva = divm2(pk2(e4.x, e4.y), dnp, ydp);
            ull pvb = divm2(pk2(e4.z, e4.w), dnp, ydp);
            float2 fa = up2(divm2(pva, spn, ysp));
            float2 fb = up2(divm2(pvb, spn, ysp));
            float r0 = fminf(fmaxf(rintf(fa.x), -127.0f), 127.0f);
            float r1 = fminf(fmaxf(rintf(fa.y), -127.0f), 127.0f);
            float r2 = fminf(fmaxf(rintf(fb.x), -127.0f), 127.0f);
            float r3 = fminf(fmaxf(rintf(fb.y), -127.0f), 127.0f);
            ulonglong2 o;
            o.x = fmul2(pk2(r0, r1), spp);
            o.y = fmul2(pk2(r2, r3), spp);
            *(ulonglong2*)&row[j*128 + lane*4] = o;
        }
    }
}

// ---------------- attention P@V: fp32 P from gmem, single-buffer 32KB V chunks ----------------
#define PV_SMEM (128*64*4)   // 32768
__global__ void __launch_bounds__(256) attnPV() {
    extern __shared__ float Vs[];
    int t = threadIdx.x;
    int tx = t & 7, ty = t >> 3;
    int bh = blockIdx.x;
    int m0 = blockIdx.y * 128;

    const float* Vg = g_Vd + (size_t)bh*SS*HDIM;

    ull acc[4][4];
    #pragma unroll
    for (int i=0;i<4;i++)
        #pragma unroll
        for (int u=0;u<4;u++) acc[i][u]=0ULL;

    const float* Pg = g_P + ((size_t)bh*SS + m0 + ty*4)*SS;
    for (int kc = 0; kc < 4; ++kc) {
        if (kc > 0) __syncthreads();
        #pragma unroll
        for (int l=0;l<8;l++)
            *(float4*)&Vs[l*1024 + t*4] = *(const float4*)(Vg + kc*8192 + l*1024 + t*4);
        __syncthreads();
        const ull* Vu = (const ull*)Vs;
        #pragma unroll 4
        for (int kb = 0; kb < 32; ++kb) {
            float pa[4][4];
            #pragma unroll
            for (int i=0;i<4;i++)
                *(float4*)pa[i] = *(const float4*)&Pg[(size_t)i*SS + kc*128 + kb*4];
            #pragma unroll
            for (int kk = 0; kk < 4; ++kk) {
                int k = kb*4 + kk;
                ulonglong2 v0 = *(const ulonglong2*)&Vu[k*32 + tx*4];
                ulonglong2 v1 = *(const ulonglong2*)&Vu[k*32 + tx*4 + 2];
                ull vp[4] = {v0.x, v0.y, v1.x, v1.y};
                #pragma unroll
                for (int i=0;i<4;i++) {
                    ull pd = dup2(pa[i][kk]);
                    acc[i][0] = ffma2(pd, vp[0], acc[i][0]);
                    acc[i][1] = ffma2(pd, vp[1], acc[i][1]);
                    acc[i][2] = ffma2(pd, vp[2], acc[i][2]);
                    acc[i][3] = ffma2(pd, vp[3], acc[i][3]);
                }
            }
        }
    }
    int b = bh / NHEADS, h = bh % NHEADS;
    #pragma unroll
    for (int i=0;i<4;i++) {
        int s = m0 + ty*4 + i;
        float* Co = g_CTX + ((size_t)(b*SS + s))*HIDDEN + h*HDIM + tx*8;
        float2 f0 = up2(acc[i][0]), f1 = up2(acc[i][1]);
        float2 f2 = up2(acc[i][2]), f3 = up2(acc[i][3]);
        *(float4*)Co     = make_float4(f0.x, f0.y, f1.x, f1.y);
        *(float4*)(Co+4) = make_float4(f2.x, f2.y, f3.x, f3.y);
    }
}

// ---------------- host: replicate np.polyfit coefficients in double ----------------
static void build_pla(PLA& p) {
    double xs[1001], ys[1001];
    double step = 10.0 / 1000.0;
    for (int j = 0; j <= 1000; j++) xs[j] = -10.0 + (double)j * step;
    xs[1000] = 0.0;
    for (int j = 0; j <= 1000; j++) ys[j] = exp(xs[j]);
    double iv[13];
    double st2 = 10.0 / 12.0;
    for (int i = 0; i < 13; i++) iv[i] = -10.0 + (double)i * st2;
    iv[12] = 0.0;
    for (int i = 0; i < 12; i++) {
        double a = iv[i], b = iv[i+1];
        double n = 0, Sx = 0, Sy = 0, Sxx = 0, Sxy = 0;
        for (int j = 0; j <= 1000; j++) {
            if (xs[j] >= a && xs[j] <= b) {
                n += 1.0; Sx += xs[j]; Sy += ys[j];
                Sxx += xs[j]*xs[j]; Sxy += xs[j]*ys[j];
            }
        }
        double m = (n*Sxy - Sx*Sy) / (n*Sxx - Sx*Sx);
        double c = (Sy - m*Sx) / n;
        p.m[i] = (float)m;
        p.c[i] = (float)c;
    }
    for (int i = 0; i < 13; i++) p.iv[i] = (float)iv[i];
}

extern "C" void kernel_launch(void* const* d_in, const int* in_sizes, int n_in,
                              void* d_out, int out_size) {
    (void)in_sizes; (void)n_in; (void)out_size;
    const float* hs = (const float*)d_in[0];
    const float* Wq = (const float*)d_in[1];
    const float* bq = (const float*)d_in[2];
    const float* Wk = (const float*)d_in[3];
    const float* bk = (const float*)d_in[4];
    const float* Wv = (const float*)d_in[5];
    const float* bv = (const float*)d_in[6];
    const float* Wo = (const float*)d_in[7];
    const float* bo = (const float*)d_in[8];

    void *pXdT, *pWdT, *pWod, *pCTX, *pCd, *pQd, *pKd, *pVd;
    cudaGetSymbolAddress(&pXdT, g_XdT);
    cudaGetSymbolAddress(&pWdT, g_WdT);
    cudaGetSymbolAddress(&pWod, g_Wod);
    cudaGetSymbolAddress(&pCTX, g_CTX);
    cudaGetSymbolAddress(&pCd, g_Cd);
    cudaGetSymbolAddress(&pQd, g_Qd);
    cudaGetSymbolAddress(&pKd, g_Kd);
    cudaGetSymbolAddress(&pVd, g_Vd);

    PLA pla;
    build_pla(pla);

    // 1) fake-quant with transposed (k-major) outputs for the QKV GEMM operands
    wrq_actT<<<512, 256>>>(hs, (float*)pXdT);
    wrq_w1T<<<192, 256>>>(Wq, Wk, (float*)pWdT);
    wrq_w2T<<<192, 256>>>(Wv, Wo, (float*)pWdT + (size_t)2*HIDDEN*HIDDEN, (float*)pWod);

    // 2) QKV projection (128x128, 2 CTAs/SM, cp.async) + per-head quantize  [launch #4]
    cudaFuncSetAttribute(gemmQKV, cudaFuncAttributeMaxDynamicSharedMemorySize, QG_SMEM);
    gemmQKV<<<dim3(18, 32), 256, QG_SMEM>>>((const float*)pXdT, (const float*)pWdT,
                                            bq, bk, bv,
                                            (float*)pQd, (float*)pKd, (float*)pVd);

    // 3) scores GEMM -> g_P ; softmax in place (4 rows/warp) ; P@V
    cudaFuncSetAttribute(attnSc, cudaFuncAttributeMaxDynamicSharedMemorySize, SC_SMEM);
    attnSc<<<dim3(96, 16), 256, SC_SMEM>>>();
    smx<<<dim3(96, 16), 256>>>(pla);
    cudaFuncSetAttribute(attnPV, cudaFuncAttributeMaxDynamicSharedMemorySize, PV_SMEM);
    attnPV<<<dim3(96, 4), 256, PV_SMEM>>>();

    // 4) fake-quant ctx rows + output projection
    wrowquant_one<<<512, 256>>>((const float*)pCTX, (float*)pCd);
    gemmOut<<<dim3(6, 64), 256>>>((const float*)pCd, (const float*)pWod, bo, (float*)d_out);
}

// round 16
// speedup vs baseline: 1.0314x; 1.0030x over previous
#include <cuda_runtime.h>
#include <cstdint>
#include <cmath>

#define HIDDEN 768
#define NHEADS 12
#define HDIM 64
#define BB 8
#define SS 512
#define ROWS (BB*SS)              // 4096
#define HEADROWS (BB*NHEADS*SS)   // 49152

// ---------------- scratch (static device allocations; no cudaMalloc) ----------------
__device__ float g_XdT[(size_t)HIDDEN*ROWS];       // dequant hidden_states, TRANSPOSED [k][m]
__device__ float g_WdT[(size_t)3*HIDDEN*HIDDEN];   // dequant Wq|Wk|Wv, each TRANSPOSED [k][n]
__device__ float g_WodT[(size_t)HIDDEN*HIDDEN];    // dequant Wo, TRANSPOSED [k][n]
__device__ float g_Qd[(size_t)HEADROWS*HDIM];      // dequant per-head q
__device__ float g_Kd[(size_t)HEADROWS*HDIM];
__device__ float g_Vd[(size_t)HEADROWS*HDIM];
__device__ float g_P [(size_t)HEADROWS*SS];        // scores, then (in-place) dequant probs
__device__ float g_CTX[(size_t)ROWS*HIDDEN];
__device__ float g_CdT[(size_t)HIDDEN*ROWS];       // dequant quantized ctx, TRANSPOSED [k][m]

struct PLA { float m[12]; float c[12]; float iv[13]; };

typedef unsigned long long ull;

// packed f32x2 ops: two independent IEEE RN ops in one instruction
__device__ __forceinline__ ull ffma2(ull a, ull b, ull c) {
    ull d;
    asm("fma.rn.f32x2 %0, %1, %2, %3;" : "=l"(d) : "l"(a), "l"(b), "l"(c));
    return d;
}
__device__ __forceinline__ ull fmul2(ull a, ull b) {
    ull d;
    asm("mul.rn.f32x2 %0, %1, %2;" : "=l"(d) : "l"(a), "l"(b));
    return d;
}
__device__ __forceinline__ float2 up2(ull v) {
    float2 r;
    asm("mov.b64 {%0, %1}, %2;" : "=f"(r.x), "=f"(r.y) : "l"(v));
    return r;
}
__device__ __forceinline__ ull dup2(float x) {
    ull d;
    asm("mov.b64 %0, {%1, %1};" : "=l"(d) : "f"(x));
    return d;
}
__device__ __forceinline__ ull pk2(float a, float b) {
    ull d;
    asm("mov.b64 %0, {%1, %2};" : "=l"(d) : "f"(a), "f"(b));
    return d;
}
// Markstein correctly-rounded division given y = __frcp_rn(d). Bit-identical to __fdiv_rn(v,d).
__device__ __forceinline__ float divm(float v, float d, float y) {
    float q0 = __fmul_rn(v, y);
    float r  = __fmaf_rn(-q0, d, v);
    return __fmaf_rn(r, y, q0);
}
// packed Markstein: dn = dup2(-d), yp = dup2(y). Per-lane bit-identical to divm.
__device__ __forceinline__ ull divm2(ull vp, ull dn, ull yp) {
    ull q0 = fmul2(vp, yp);
    ull r  = ffma2(q0, dn, vp);
    return ffma2(r, yp, q0);
}
// cp.async 16B gmem -> smem
__device__ __forceinline__ void cpa16(void* smp, const void* gmp) {
    unsigned s = (unsigned)__cvta_generic_to_shared(smp);
    asm volatile("cp.async.cg.shared.global [%0], [%1], 16;" :: "r"(s), "l"(gmp));
}

// ---------------- warp-per-row (768) quantize: compute v[24] in regs ----------------
__device__ __forceinline__ void wrow_calc(const float* __restrict__ x, float* v, int lane) {
    #pragma unroll
    for (int j=0;j<6;j++) *(float4*)&v[j*4] = *(const float4*)&x[j*128 + lane*4];
    float mx = fabsf(v[0]);
    #pragma unroll
    for (int j=1;j<24;j++) mx = fmaxf(mx, fabsf(v[j]));
    #pragma unroll
    for (int o=16;o>0;o>>=1) mx = fmaxf(mx, __shfl_xor_sync(0xffffffffu, mx, o));
    float sc = __fdiv_rn(mx, 127.0f);
    if (sc == 0.0f) sc = 1.0f;
    float y = __frcp_rn(sc);
    ull scn = dup2(-sc), yp = dup2(y), scp = dup2(sc);
    #pragma unroll
    for (int j=0;j<12;j++) {
        ull q = divm2(pk2(v[2*j], v[2*j+1]), scn, yp);
        float2 f = up2(q);
        float r0 = fminf(fmaxf(rintf(f.x), -127.0f), 127.0f);
        float r1 = fminf(fmaxf(rintf(f.y), -127.0f), 127.0f);
        float2 o = up2(fmul2(pk2(r0, r1), scp));
        v[2*j] = o.x; v[2*j+1] = o.y;
    }
}

// transposing block body: 8 rows quantized -> dstT[k][n0..n0+7], leading dim ldT
__device__ __forceinline__ void wrowT_block(const float* __restrict__ srcbase,
                                            float* __restrict__ dstT,
                                            int n0, int ldT) {
    __shared__ float S[8][772];
    int t = threadIdx.x, w = t >> 5, lane = t & 31;
    float v[24];
    wrow_calc(srcbase + (size_t)(n0 + w)*HIDDEN, v, lane);
    #pragma unroll
    for (int j=0;j<6;j++) *(float4*)&S[w][j*128 + lane*4] = *(float4*)&v[j*4];
    __syncthreads();
    #pragma unroll
    for (int i = 0; i < 6; ++i) {
        int c = t + i*256;                 // 0..1535
        int k = c >> 1, half = (c & 1) * 4;
        float4 o;
        o.x = S[half+0][k]; o.y = S[half+1][k];
        o.z = S[half+2][k]; o.w = S[half+3][k];
        *(float4*)&dstT[(size_t)k*ldT + n0 + half] = o;
    }
}

// activations -> XdT (4096 rows -> columns)
__global__ void __launch_bounds__(256) wrq_actT(const float* __restrict__ x,
                                                float* __restrict__ xdT) {
    wrowT_block(x, xdT, blockIdx.x*8, ROWS);
}
// Wq + Wk -> WdT mats 0,1 (transposed)
__global__ void __launch_bounds__(256) wrq_w1T(const float* __restrict__ wq,
                                               const float* __restrict__ wk,
                                               float* __restrict__ wdT) {
    int rowg = blockIdx.x * 8;
    if (rowg < 768) wrowT_block(wq, wdT, rowg, HIDDEN);
    else            wrowT_block(wk, wdT + (size_t)HIDDEN*HIDDEN, rowg - 768, HIDDEN);
}
// Wv -> WdT mat 2 (transposed); Wo -> WodT (transposed)
__global__ void __launch_bounds__(256) wrq_w2T(const float* __restrict__ wv,
                                               const float* __restrict__ wo,
                                               float* __restrict__ wdT2,
                                               float* __restrict__ wodT) {
    int rowg = blockIdx.x * 8;
    if (rowg < 768) wrowT_block(wv, wdT2, rowg, HIDDEN);
    else            wrowT_block(wo, wodT, rowg - 768, HIDDEN);
}
// ctx -> CdT (4096 rows -> columns)
__global__ void __launch_bounds__(256) wrq_ctxT(const float* __restrict__ src,
                                                float* __restrict__ cdT) {
    wrowT_block(src, cdT, blockIdx.x*8, ROWS);
}

// ---------------- GEMM 128x128, BK=32, 8m x 8n per thread, 2 CTAs/SM, 2-stage cp.async ----------------
#define QG_PAD 132
#define QG_STG (2*32*QG_PAD)                     // A+B floats per stage
#define QG_SMEM (2*QG_STG*4)                     // 67584 B
// QUANT=1: per-head quantize epilogue -> Qd/Kd/Vd.  QUANT=0: bias + store to C.
template<int QUANT>
__global__ void __launch_bounds__(256,2) gemmBK32(const float* __restrict__ AT, int lda,
                                                  const float* __restrict__ BT,
                                                  const float* __restrict__ b0,
                                                  const float* __restrict__ b1,
                                                  const float* __restrict__ b2,
                                                  float* __restrict__ C,
                                                  float* __restrict__ Qd,
                                                  float* __restrict__ Kd,
                                                  float* __restrict__ Vd) {
    extern __shared__ float sm[];
    int t = threadIdx.x;
    int m0 = blockIdx.y * 128;
    int n0 = blockIdx.x * 128;
    int w = t >> 5, lane = t & 31;
    int wm = w & 3, wn = w >> 2;           // warp tile: 32m x 64n
    int lm = lane & 3, ln = lane >> 2;     // lane tile: 8m x 8n
    int tsel = QUANT ? (n0 / 768) : 0;
    int nrel = QUANT ? (n0 % 768) : n0;
    const float* Bt = BT + (size_t)tsel*HIDDEN*HIDDEN + nrel;

    ull acc[4][8];
    #pragma unroll
    for (int p=0;p<4;p++)
        #pragma unroll
        for (int j=0;j<8;j++) acc[p][j]=0ULL;

    int ar = t >> 5, ac = (t & 31) * 4;    // rows ar + l*8 (l=0..3), col ac
    #define G32_CPA(kt, stg) do { \
        float* Ab = sm + (stg)*QG_STG; \
        float* Bb = Ab + 32*QG_PAD; \
        _Pragma("unroll") \
        for (int l=0;l<4;l++) { \
            int r = ar + l*8; \
            cpa16(&Ab[r*QG_PAD + ac], &AT[(size_t)((kt)*32 + r)*lda + m0 + ac]); \
            cpa16(&Bb[r*QG_PAD + ac], &Bt[(size_t)((kt)*32 + r)*HIDDEN + ac]); \
        } \
        asm volatile("cp.async.commit_group;"); \
    } while(0)

    G32_CPA(0, 0);

    int aull = wm*16 + lm*4;
    int boff = wn*64 + ln*8;
    for (int kt = 0; kt < 24; ++kt) {
        int buf = kt & 1;
        if (kt < 23) {
            G32_CPA(kt+1, buf ^ 1);
            asm volatile("cp.async.wait_group 1;");
        } else {
            asm volatile("cp.async.wait_group 0;");
        }
        __syncthreads();
        const float* Ab = sm + buf*QG_STG;
        const float* Bb = Ab + 32*QG_PAD;
        #pragma unroll 16
        for (int k = 0; k < 32; ++k) {     // ascending k; fused fma per output
            const ull* Au = (const ull*)(Ab + k*QG_PAD);
            ulonglong2 a0 = *(const ulonglong2*)&Au[aull];
            ulonglong2 a1 = *(const ulonglong2*)&Au[aull+2];
            ull am[4] = {a0.x, a0.y, a1.x, a1.y};
            const float* Brow = Bb + k*QG_PAD + boff;
            float4 bl = *(const float4*)Brow;
            float4 bh = *(const float4*)(Brow+4);
            ull bd[8];
            bd[0]=dup2(bl.x); bd[1]=dup2(bl.y); bd[2]=dup2(bl.z); bd[3]=dup2(bl.w);
            bd[4]=dup2(bh.x); bd[5]=dup2(bh.y); bd[6]=dup2(bh.z); bd[7]=dup2(bh.w);
            #pragma unroll
            for (int p=0;p<4;p++)
                #pragma unroll
                for (int j=0;j<8;j++)
                    acc[p][j] = ffma2(am[p], bd[j], acc[p][j]);
        }
        if (kt < 23) __syncthreads();
    }

    if (QUANT) {
        // epilogue: bias + per-head (64) quantize -> Qd/Kd/Vd
        const float* bias = (tsel==0) ? b0 : (tsel==1 ? b1 : b2);
        float* dstbase = (tsel==0) ? Qd : (tsel==1 ? Kd : Vd);
        int hh = (nrel >> 6) + wn;
        int cb = nrel + wn*64 + ln*8;
        #pragma unroll
        for (int p=0;p<4;p++) {
            float ve[8], vo[8];
            #pragma unroll
            for (int j=0;j<8;j++) {
                float2 f = up2(acc[p][j]);
                ve[j] = __fadd_rn(f.x, bias[cb+j]);
                vo[j] = __fadd_rn(f.y, bias[cb+j]);
            }
            #pragma unroll
            for (int half=0; half<2; ++half) {
                float* v = half ? vo : ve;
                int gm = m0 + wm*32 + lm*8 + 2*p + half;
                float mxv = fabsf(v[0]);
                #pragma unroll
                for (int j=1;j<8;j++) mxv = fmaxf(mxv, fabsf(v[j]));
                mxv = fmaxf(mxv, __shfl_xor_sync(0xffffffffu, mxv, 4));
                mxv = fmaxf(mxv, __shfl_xor_sync(0xffffffffu, mxv, 8));
                mxv = fmaxf(mxv, __shfl_xor_sync(0xffffffffu, mxv, 16));
                float sc = __fdiv_rn(mxv, 127.0f);
                if (sc == 0.0f) sc = 1.0f;
                float y = __frcp_rn(sc);
                float q[8];
                #pragma unroll
                for (int j=0;j<8;j++)
                    q[j] = __fmul_rn(fminf(fmaxf(rintf(divm(v[j], sc, y)), -127.0f), 127.0f), sc);
                int b = gm >> 9, s = gm & 511;
                float* drow = dstbase + ((size_t)((b*NHEADS + hh)*SS + s))*HDIM + ln*8;
                *(float4*)drow       = make_float4(q[0],q[1],q[2],q[3]);
                *(float4*)(drow + 4) = make_float4(q[4],q[5],q[6],q[7]);
            }
        }
    } else {
        int cb = n0 + wn*64 + ln*8;
        #pragma unroll
        for (int p=0;p<4;p++) {
            float ve[8], vo[8];
            #pragma unroll
            for (int j=0;j<8;j++) {
                float2 f = up2(acc[p][j]);
                ve[j] = __fadd_rn(f.x, b0[cb+j]);
                vo[j] = __fadd_rn(f.y, b0[cb+j]);
            }
            int gm = m0 + wm*32 + lm*8 + 2*p;
            float* ce = C + (size_t)gm*768 + cb;
            float* co = C + (size_t)(gm+1)*768 + cb;
            *(float4*)ce     = make_float4(ve[0],ve[1],ve[2],ve[3]);
            *(float4*)(ce+4) = make_float4(ve[4],ve[5],ve[6],ve[7]);
            *(float4*)co     = make_float4(vo[0],vo[1],vo[2],vo[3]);
            *(float4*)(co+4) = make_float4(vo[4],vo[5],vo[6],vo[7]);
        }
    }
}

// ---------------- attention scores GEMM: S[m,n] = (q[m,:].k[n,:]) * 0.125 -> g_P ----------------
#define SC_SMEM (2*64*128*4)   // 65536
__global__ void __launch_bounds__(256,2) attnSc() {
    extern __shared__ float sm[];
    float* Qs = sm;            // [d 64][m 128]
    float* Ks = sm + 64*128;   // [d 64][n 128]
    int t = threadIdx.x;
    int bh = blockIdx.x;
    int m0 = (blockIdx.y & 3) * 128;
    int n0 = (blockIdx.y >> 2) * 128;
    int w = t >> 5, lane = t & 31;
    int wm = w & 3, wn = w >> 2;
    int lm = lane & 3, ln = lane >> 2;

    {
        int r = t & 127, d0 = (t >> 7) * 32;
        const float* Qg = g_Qd + ((size_t)bh*SS + m0 + r)*HDIM + d0;
        const float* Kg = g_Kd + ((size_t)bh*SS + n0 + r)*HDIM + d0;
        #pragma unroll
        for (int j=0;j<8;j++) {
            float4 q = *(const float4*)(Qg + j*4);
            Qs[(d0+j*4+0)*128 + r] = q.x; Qs[(d0+j*4+1)*128 + r] = q.y;
            Qs[(d0+j*4+2)*128 + r] = q.z; Qs[(d0+j*4+3)*128 + r] = q.w;
            float4 k = *(const float4*)(Kg + j*4);
            Ks[(d0+j*4+0)*128 + r] = k.x; Ks[(d0+j*4+1)*128 + r] = k.y;
            Ks[(d0+j*4+2)*128 + r] = k.z; Ks[(d0+j*4+3)*128 + r] = k.w;
        }
    }
    __syncthreads();

    ull acc[4][8];
    #pragma unroll
    for (int p=0;p<4;p++)
        #pragma unroll
        for (int j=0;j<8;j++) acc[p][j]=0ULL;

    int aull = wm*16 + lm*4;
    int boff = wn*64 + ln*8;
    #pragma unroll 8
    for (int d = 0; d < 64; ++d) {
        const ull* Au = (const ull*)(Qs + d*128);
        ulonglong2 a0 = *(const ulonglong2*)&Au[aull];
        ulonglong2 a1 = *(const ulonglong2*)&Au[aull+2];
        ull am[4] = {a0.x, a0.y, a1.x, a1.y};
        const float* Brow = Ks + d*128 + boff;
        float4 bl = *(const float4*)Brow;
        float4 bh = *(const float4*)(Brow+4);
        ull bd[8];
        bd[0]=dup2(bl.x); bd[1]=dup2(bl.y); bd[2]=dup2(bl.z); bd[3]=dup2(bl.w);
        bd[4]=dup2(bh.x); bd[5]=dup2(bh.y); bd[6]=dup2(bh.z); bd[7]=dup2(bh.w);
        #pragma unroll
        for (int p=0;p<4;p++)
            #pragma unroll
            for (int j=0;j<8;j++)
                acc[p][j] = ffma2(am[p], bd[j], acc[p][j]);
    }

    int cb = n0 + wn*64 + ln*8;
    #pragma unroll
    for (int p=0;p<4;p++) {
        float ve[8], vo[8];
        #pragma unroll
        for (int j=0;j<8;j++) {
            float2 f = up2(acc[p][j]);
            ve[j] = __fmul_rn(f.x, 0.125f);
            vo[j] = __fmul_rn(f.y, 0.125f);
        }
        int gm = m0 + wm*32 + lm*8 + 2*p;
        float* se = g_P + ((size_t)bh*SS + gm)*SS + cb;
        float* so = g_P + ((size_t)bh*SS + gm + 1)*SS + cb;
        *(float4*)se     = make_float4(ve[0],ve[1],ve[2],ve[3]);
        *(float4*)(se+4) = make_float4(ve[4],ve[5],ve[6],ve[7]);
        *(float4*)so     = make_float4(vo[0],vo[1],vo[2],vo[3]);
        *(float4*)(so+4) = make_float4(vo[4],vo[5],vo[6],vo[7]);
    }
}

// ---------------- softmax (in-place on g_P): 4 rows per warp, batched strict sums ----------------
__global__ void __launch_bounds__(256) smx(PLA pla) {
    __shared__ float eb[8][4][512];
    __shared__ float2 sm_mc[12];
    __shared__ float2 sm_iv2[12];
    int t = threadIdx.x, w = t >> 5, lane = t & 31;
    if (t < 12) {
        sm_mc[t]  = make_float2(pla.m[t], pla.c[t]);
        sm_iv2[t] = make_float2(pla.iv[t], pla.iv[t+1]);
    }
    __syncthreads();
    int bh = blockIdx.x;
    int rowbase = blockIdx.y*32 + w*4;
    float amax[4];

    for (int r4 = 0; r4 < 4; ++r4) {
        const float* row = g_P + ((size_t)bh*SS + rowbase + r4)*SS;
        float v[16];
        #pragma unroll
        for (int j=0;j<4;j++) *(float4*)&v[j*4] = *(const float4*)&row[j*128 + lane*4];
        float mx = v[0];
        #pragma unroll
        for (int j=1;j<16;j++) mx = fmaxf(mx, v[j]);
        #pragma unroll
        for (int o=16;o>0;o>>=1) mx = fmaxf(mx, __shfl_xor_sync(0xffffffffu, mx, o));
        float am = 0.0f;
        #pragma unroll
        for (int j = 0; j < 16; j++) {
            float sh = __fadd_rn(v[j], -mx);
            float fr = rintf(__fmul_rn(sh, 67108864.0f));
            float fx = __fmul_rn(fr, 1.4901161193847656e-8f);
            float xc = fmaxf(fx, -10.0f);
            int idx = (int)floorf(__fmul_rn(__fadd_rn(xc, 10.0f), 1.2f));
            idx = idx < 0 ? 0 : (idx > 11 ? 11 : idx);
            float2 bnd = sm_iv2[idx];
            if (idx > 0 && xc < bnd.x) idx--;
            else if (idx < 11 && xc >= bnd.y) idx++;
            float2 mc = sm_mc[idx];
            float e = __fadd_rn(__fmul_rn(mc.x, xc), mc.y);
            v[j] = e;
            am = fmaxf(am, fabsf(e));
        }
        #pragma unroll
        for (int j=0;j<4;j++) *(float4*)&eb[w][r4][j*128 + lane*4] = *(float4*)&v[j*4];
        #pragma unroll
        for (int o=16;o>0;o>>=1) am = fmaxf(am, __shfl_xor_sync(0xffffffffu, am, o));
        amax[r4] = am;
    }
    __syncwarp();

    float ssum = 0.0f;
    if (lane < 4) {
        const float* er = eb[w][lane];
        #pragma unroll 8
        for (int i = 0; i < 512; i++) ssum = __fadd_rn(ssum, er[i]);
    }
    __syncwarp();

    for (int r4 = 0; r4 < 4; ++r4) {
        float denom = __fadd_rn(__shfl_sync(0xffffffffu, ssum, r4), 1e-9f);
        float yd = __frcp_rn(denom);
        ull dnp = dup2(-denom), ydp = dup2(yd);
        float qmx = divm(amax[r4], denom, yd);
        float sp = __fdiv_rn(qmx, 127.0f);
        if (sp == 0.0f) sp = 1.0f;
        float ys = __frcp_rn(sp);
        ull spn = dup2(-sp), ysp = dup2(ys), spp = dup2(sp);
        float* row = g_P + ((size_t)bh*SS + rowbase + r4)*SS;
        const float* er = eb[w][r4];
        #pragma unroll
        for (int j = 0; j < 4; ++j) {
            float4 e4 = *(const float4*)&er[j*128 + lane*4];
            ull pva = divm2(pk2(e4.x, e4.y), dnp, ydp);
            ull pvb = divm2(pk2(e4.z, e4.w), dnp, ydp);
            float2 fa = up2(divm2(pva, spn, ysp));
            float2 fb = up2(divm2(pvb, spn, ysp));
            float r0 = fminf(fmaxf(rintf(fa.x), -127.0f), 127.0f);
            float r1 = fminf(fmaxf(rintf(fa.y), -127.0f), 127.0f);
            float r2 = fminf(fmaxf(rintf(fb.x), -127.0f), 127.0f);
            float r3 = fminf(fmaxf(rintf(fb.y), -127.0f), 127.0f);
            ulonglong2 o;
            o.x = fmul2(pk2(r0, r1), spp);
            o.y = fmul2(pk2(r2, r3), spp);
            *(ulonglong2*)&row[j*128 + lane*4] = o;
        }
    }
}

// ---------------- attention P@V: fp32 P from gmem, single-buffer 32KB V chunks ----------------
#define PV_SMEM (128*64*4)   // 32768
__global__ void __launch_bounds__(256) attnPV() {
    extern __shared__ float Vs[];
    int t = threadIdx.x;
    int tx = t & 7, ty = t >> 3;
    int bh = blockIdx.x;
    int m0 = blockIdx.y * 128;

    const float* Vg = g_Vd + (size_t)bh*SS*HDIM;

    ull acc[4][4];
    #pragma unroll
    for (int i=0;i<4;i++)
        #pragma unroll
        for (int u=0;u<4;u++) acc[i][u]=0ULL;

    const float* Pg = g_P + ((size_t)bh*SS + m0 + ty*4)*SS;
    for (int kc = 0; kc < 4; ++kc) {
        if (kc > 0) __syncthreads();
        #pragma unroll
        for (int l=0;l<8;l++)
            *(float4*)&Vs[l*1024 + t*4] = *(const float4*)(Vg + kc*8192 + l*1024 + t*4);
        __syncthreads();
        const ull* Vu = (const ull*)Vs;
        #pragma unroll 4
        for (int kb = 0; kb < 32; ++kb) {
            float pa[4][4];
            #pragma unroll
            for (int i=0;i<4;i++)
                *(float4*)pa[i] = *(const float4*)&Pg[(size_t)i*SS + kc*128 + kb*4];
            #pragma unroll
            for (int kk = 0; kk < 4; ++kk) {
                int k = kb*4 + kk;
                ulonglong2 v0 = *(const ulonglong2*)&Vu[k*32 + tx*4];
                ulonglong2 v1 = *(const ulonglong2*)&Vu[k*32 + tx*4 + 2];
                ull vp[4] = {v0.x, v0.y, v1.x, v1.y};
                #pragma unroll
                for (int i=0;i<4;i++) {
                    ull pd = dup2(pa[i][kk]);
                    acc[i][0] = ffma2(pd, vp[0], acc[i][0]);
                    acc[i][1] = ffma2(pd, vp[1], acc[i][1]);
                    acc[i][2] = ffma2(pd, vp[2], acc[i][2]);
                    acc[i][3] = ffma2(pd, vp[3], acc[i][3]);
                }
            }
        }
    }
    int b = bh / NHEADS, h = bh % NHEADS;
    #pragma unroll
    for (int i=0;i<4;i++) {
        int s = m0 + ty*4 + i;
        float* Co = g_CTX + ((size_t)(b*SS + s))*HIDDEN + h*HDIM + tx*8;
        float2 f0 = up2(acc[i][0]), f1 = up2(acc[i][1]);
        float2 f2 = up2(acc[i][2]), f3 = up2(acc[i][3]);
        *(float4*)Co     = make_float4(f0.x, f0.y, f1.x, f1.y);
        *(float4*)(Co+4) = make_float4(f2.x, f2.y, f3.x, f3.y);
    }
}

// ---------------- host: replicate np.polyfit coefficients in double ----------------
static void build_pla(PLA& p) {
    double xs[1001], ys[1001];
    double step = 10.0 / 1000.0;
    for (int j = 0; j <= 1000; j++) xs[j] = -10.0 + (double)j * step;
    xs[1000] = 0.0;
    for (int j = 0; j <= 1000; j++) ys[j] = exp(xs[j]);
    double iv[13];
    double st2 = 10.0 / 12.0;
    for (int i = 0; i < 13; i++) iv[i] = -10.0 + (double)i * st2;
    iv[12] = 0.0;
    for (int i = 0; i < 12; i++) {
        double a = iv[i], b = iv[i+1];
        double n = 0, Sx = 0, Sy = 0, Sxx = 0, Sxy = 0;
        for (int j = 0; j <= 1000; j++) {
            if (xs[j] >= a && xs[j] <= b) {
                n += 1.0; Sx += xs[j]; Sy += ys[j];
                Sxx += xs[j]*xs[j]; Sxy += xs[j]*ys[j];
            }
        }
        double m = (n*Sxy - Sx*Sy) / (n*Sxx - Sx*Sx);
        double c = (Sy - m*Sx) / n;
        p.m[i] = (float)m;
        p.c[i] = (float)c;
    }
    for (int i = 0; i < 13; i++) p.iv[i] = (float)iv[i];
}

extern "C" void kernel_launch(void* const* d_in, const int* in_sizes, int n_in,
                              void* d_out, int out_size) {
    (void)in_sizes; (void)n_in; (void)out_size;
    const float* hs = (const float*)d_in[0];
    const float* Wq = (const float*)d_in[1];
    const float* bq = (const float*)d_in[2];
    const float* Wk = (const float*)d_in[3];
    const float* bk = (const float*)d_in[4];
    const float* Wv = (const float*)d_in[5];
    const float* bv = (const float*)d_in[6];
    const float* Wo = (const float*)d_in[7];
    const float* bo = (const float*)d_in[8];

    void *pXdT, *pWdT, *pWodT, *pCTX, *pCdT, *pQd, *pKd, *pVd;
    cudaGetSymbolAddress(&pXdT, g_XdT);
    cudaGetSymbolAddress(&pWdT, g_WdT);
    cudaGetSymbolAddress(&pWodT, g_WodT);
    cudaGetSymbolAddress(&pCTX, g_CTX);
    cudaGetSymbolAddress(&pCdT, g_CdT);
    cudaGetSymbolAddress(&pQd, g_Qd);
    cudaGetSymbolAddress(&pKd, g_Kd);
    cudaGetSymbolAddress(&pVd, g_Vd);

    PLA pla;
    build_pla(pla);

    // 1) fake-quant with transposed (k-major) outputs for all GEMM operands
    wrq_actT<<<512, 256>>>(hs, (float*)pXdT);
    wrq_w1T<<<192, 256>>>(Wq, Wk, (float*)pWdT);
    wrq_w2T<<<192, 256>>>(Wv, Wo, (float*)pWdT + (size_t)2*HIDDEN*HIDDEN, (float*)pWodT);

    // 2) QKV projection (128x128 BK=32, 2 CTAs/SM, cp.async) + per-head quantize  [launch #4]
    cudaFuncSetAttribute(gemmBK32<1>, cudaFuncAttributeMaxDynamicSharedMemorySize, QG_SMEM);
    gemmBK32<1><<<dim3(18, 32), 256, QG_SMEM>>>((const float*)pXdT, ROWS, (const float*)pWdT,
                                                bq, bk, bv, nullptr,
                                                (float*)pQd, (float*)pKd, (float*)pVd);

    // 3) scores GEMM -> g_P ; softmax in place (4 rows/warp) ; P@V
    cudaFuncSetAttribute(attnSc, cudaFuncAttributeMaxDynamicSharedMemorySize, SC_SMEM);
    attnSc<<<dim3(96, 16), 256, SC_SMEM>>>();
    smx<<<dim3(96, 16), 256>>>(pla);
    cudaFuncSetAttribute(attnPV, cudaFuncAttributeMaxDynamicSharedMemorySize, PV_SMEM);
    attnPV<<<dim3(96, 4), 256, PV_SMEM>>>();

    // 4) fake-quant ctx rows (transposed) + output projection (same BK=32 GEMM)
    wrq_ctxT<<<512, 256>>>((const float*)pCTX, (float*)pCdT);
    cudaFuncSetAttribute(gemmBK32<0>, cudaFuncAttributeMaxDynamicSharedMemorySize, QG_SMEM);
    gemmBK32<0><<<dim3(6, 32), 256, QG_SMEM>>>((const float*)pCdT, ROWS, (const float*)pWodT,
                                               bo, nullptr, nullptr, (float*)d_out,
                                               nullptr, nullptr, nullptr);
}